// round 14
// baseline (speedup 1.0000x reference)
#include <cuda_runtime.h>
#include <cuda_fp16.h>
#include <math.h>
#include <stdint.h>

#define BS_    128
#define SEQ    32
#define DIMN   512
#define P_     10
#define NTOP   6

#define KBIG   10000
#define KBIGP  10048
#define KCONV  2560
#define KPSL   1024

// ---------------- device scratch ------------------------------------------------
__device__ float  g_X  [BS_ * SEQ * DIMN];
__device__ __half g_Xh [BS_ * SEQ * DIMN];
__device__ __half g_Y1h[BS_ * SEQ * DIMN];
__device__ float  g_psl[BS_ * 2 * P_ * DIMN];

__device__ __half g_A  [(size_t)4096 * KBIGP];
__device__ __half g_Ap [2560 * KPSL];
__device__ __half g_Wc [(size_t)512 * KBIGP];
__device__ __half g_W1 [512 * KCONV];
__device__ __half g_W2 [512 * KCONV];
__device__ __half g_Wp [512 * KPSL];
__device__ __half g_Wv [512 * DIMN];
__device__ __half g_Ws [512 * DIMN];

__device__ __half g_SptH [BS_ * NTOP * DIMN];
__device__ __half g_SaggH[BS_ * NTOP * DIMN];
__device__ float  g_V  [BS_ * NTOP * DIMN];
__device__ float  g_Sv [BS_ * NTOP * DIMN];

// ---------------- ptx helpers -----------------------------------------------------
__device__ __forceinline__ void cp16(uint32_t sa, const void* g) {
    asm volatile("cp.async.cg.shared.global [%0], [%1], 16;\n" :: "r"(sa), "l"(g) : "memory");
}
__device__ __forceinline__ void cp16z(uint32_t sa, const void* g, uint32_t srcsize) {
    asm volatile("cp.async.cg.shared.global [%0], [%1], 16, %2;\n"
                 :: "r"(sa), "l"(g), "r"(srcsize) : "memory");
}
__device__ __forceinline__ void cp_commit() {
    asm volatile("cp.async.commit_group;\n" ::: "memory");
}
template<int N> __device__ __forceinline__ void cp_wait() {
    asm volatile("cp.async.wait_group %0;\n" :: "n"(N) : "memory");
}
__device__ __forceinline__ uint32_t smem_u32(const void* p) {
    uint32_t a;
    asm("{ .reg .u64 t; cvta.to.shared.u64 t, %1; cvt.u32.u64 %0, t; }" : "=r"(a) : "l"(p));
    return a;
}
__device__ __forceinline__ void ldmx4(uint32_t* r, uint32_t addr) {
    asm volatile("ldmatrix.sync.aligned.m8n8.x4.shared.b16 {%0,%1,%2,%3}, [%4];"
                 : "=r"(r[0]), "=r"(r[1]), "=r"(r[2]), "=r"(r[3]) : "r"(addr));
}
// f16-accumulator HMMA: D(f16x2 x2) = A*B + D
__device__ __forceinline__ void mma_h(uint32_t* d,
    uint32_t a0, uint32_t a1, uint32_t a2, uint32_t a3,
    uint32_t b0, uint32_t b1)
{
    asm volatile(
        "mma.sync.aligned.m16n8k16.row.col.f16.f16.f16.f16 "
        "{%0,%1}, {%2,%3,%4,%5}, {%6,%7}, {%0,%1};"
        : "+r"(d[0]), "+r"(d[1])
        : "r"(a0), "r"(a1), "r"(a2), "r"(a3), "r"(b0), "r"(b1));
}
__device__ __forceinline__ void cvt8(__half* h, const float* s) {
    const float4 v0 = *(const float4*)s;
    const float4 v1 = *(const float4*)(s + 4);
    h[0] = __float2half(v0.x); h[1] = __float2half(v0.y);
    h[2] = __float2half(v0.z); h[3] = __float2half(v0.w);
    h[4] = __float2half(v1.x); h[5] = __float2half(v1.y);
    h[6] = __float2half(v1.z); h[7] = __float2half(v1.w);
}

// ---------------- mega conversion kernel (R12) -------------------------------------
#define CPR_BIG  (KBIGP / 8)
#define S0N (4096 * CPR_BIG)
#define S1N (512 * CPR_BIG)
#define S2N (512 * (KCONV / 8))
#define S3N S2N
#define S4N (512 * (KPSL / 8))
#define S5N (2560 * (KPSL / 8))
#define S6N (512 * (DIMN / 8))
#define S7N S6N
#define E0 S0N
#define E1 (E0 + S1N)
#define E2 (E1 + S2N)
#define E3 (E2 + S3N)
#define E4 (E3 + S4N)
#define E5 (E4 + S5N)
#define E6 (E5 + S6N)
#define E7 (E6 + S7N)

__global__ void __launch_bounds__(256) mega_convert(
    const float* __restrict__ inputs, const float* __restrict__ conv_w,
    const float* __restrict__ res_w1, const float* __restrict__ res_w2,
    const float* __restrict__ psl_w,
    const float* __restrict__ obj, const float* __restrict__ motion,
    const float* __restrict__ sv_w, const float* __restrict__ ss_w,
    __half* __restrict__ A, __half* __restrict__ Wc,
    __half* __restrict__ W1, __half* __restrict__ W2,
    __half* __restrict__ Wp, __half* __restrict__ Ap,
    __half* __restrict__ Wv, __half* __restrict__ Ws)
{
    const int stride = gridDim.x * blockDim.x;
    for (int i = blockIdx.x * blockDim.x + threadIdx.x; i < E7; i += stride) {
        __half h[8];
        if (i < E0) {
            const int row = i / CPR_BIG, ch = i - row * CPR_BIG;
            const int c8 = ch << 3;
            if (c8 < KBIG) cvt8(h, inputs + (size_t)row * KBIG + c8);
            else { h[0]=h[1]=h[2]=h[3]=h[4]=h[5]=h[6]=h[7]=__float2half(0.f); }
            *(uint4*)(A + (size_t)row * KBIGP + c8) = *(const uint4*)h;
        } else if (i < E1) {
            const int j = i - E0;
            const int row = j / CPR_BIG, ch = j - row * CPR_BIG;
            const int c8 = ch << 3;
            if (c8 < KBIG) cvt8(h, conv_w + (size_t)row * KBIG + c8);
            else { h[0]=h[1]=h[2]=h[3]=h[4]=h[5]=h[6]=h[7]=__float2half(0.f); }
            *(uint4*)(Wc + (size_t)row * KBIGP + c8) = *(const uint4*)h;
        } else if (i < E3) {
            const int j = (i < E2) ? (i - E1) : (i - E2);
            const float* src = (i < E2) ? res_w1 : res_w2;
            __half* dst = (i < E2) ? W1 : W2;
            const int dout = j / 320, ch = j - dout * 320;
            const int k0 = ch << 3;
            const int tap = k0 >> 9, din0 = k0 & 511;
            const float* s = src + dout * KCONV + din0 * 5 + tap;
#pragma unroll
            for (int e = 0; e < 8; e++) h[e] = __float2half(s[e * 5]);
            *(uint4*)(dst + dout * KCONV + k0) = *(const uint4*)h;
        } else if (i < E4) {
            const int j = i - E3;
            const int row = j >> 7, c8 = (j & 127) << 3;
            cvt8(h, psl_w + (size_t)row * KPSL + c8);
            *(uint4*)(Wp + (size_t)row * KPSL + c8) = *(const uint4*)h;
        } else if (i < E5) {
            const int j = i - E4;
            const int row = j >> 7, c8 = (j & 127) << 3;
            const int b = row / 20, p = row - b * 20;
            const float* s = (p < P_) ? obj    + ((size_t)(b * P_ + p      )) * KPSL + c8
                                      : motion + ((size_t)(b * P_ + p - P_ )) * KPSL + c8;
            cvt8(h, s);
            *(uint4*)(Ap + (size_t)row * KPSL + c8) = *(const uint4*)h;
        } else if (i < E6) {
            const int j = i - E5;
            const int row = j >> 6, c8 = (j & 63) << 3;
            cvt8(h, sv_w + (size_t)row * DIMN + c8);
            *(uint4*)(Wv + (size_t)row * DIMN + c8) = *(const uint4*)h;
        } else {
            const int j = i - E6;
            const int row = j >> 6, c8 = (j & 63) << 3;
            cvt8(h, ss_w + (size_t)row * DIMN + c8);
            *(uint4*)(Ws + (size_t)row * DIMN + c8) = *(const uint4*)h;
        }
    }
}

// ---------------- mma.sync GEMM, BK=64, fp16 accumulate + periodic f32 flush ------
#define TILEN   64
#define PITCH   144u
#define MATA    (128u * PITCH)
#define STAGEB  (MATA + 64u * PITCH)
#define FLUSH   4              // flush f16 acc to f32 every 4 chunks (256 k)

template<int AMODE>
__device__ __forceinline__ void load_stage(
    uint32_t sb, int t,
    const __half* __restrict__ A, const __half* __restrict__ B,
    int row0, int col0, int K, int k0)
{
#pragma unroll
    for (int j = 0; j < 8; j++) {
        const int cid = j * 128 + t;
        const int r  = cid >> 3, ch = cid & 7;
        const uint32_t sa = sb + (uint32_t)(r * PITCH + ch * 16);
        if (AMODE == 0) {
            cp16(sa, A + (size_t)(row0 + r) * K + k0 + ch * 8);
        } else {
            const int grow = row0 + r;
            const int tap  = k0 >> 9;
            const int din0 = (k0 & 511) + ch * 8;
            const int s2   = (grow & 31) + tap - 2;
            const uint32_t ok = (s2 >= 0 && s2 < SEQ) ? 16u : 0u;
            const int srow = ok ? (grow + tap - 2) : grow;
            cp16z(sa, A + (size_t)srow * DIMN + din0, ok);
        }
    }
#pragma unroll
    for (int j = 0; j < 4; j++) {
        const int cid = j * 128 + t;
        const int r  = cid >> 3, ch = cid & 7;
        cp16(sb + MATA + (uint32_t)(r * PITCH + ch * 16),
             B + (size_t)(col0 + r) * K + k0 + ch * 8);
    }
}

template<int AMODE, int EPI>
__global__ void __launch_bounds__(128, 3) gemm_mma(
    const __half* __restrict__ A, const __half* __restrict__ B,
    const float* __restrict__ bias, float* __restrict__ C,
    __half* __restrict__ H, int K)
{
    extern __shared__ char smem[];
    const uint32_t sbase = smem_u32(smem);
    const int t = threadIdx.x;
    const int wid = t >> 5, lane = t & 31;
    const int warp_m = wid >> 1, warp_n = wid & 1;
    const int tr = lane >> 2, tc = lane & 3;
    const int row0 = blockIdx.y * 128;
    const int col0 = blockIdx.x * TILEN;

    const uint32_t a_off = (uint32_t)((warp_m * 64 + (lane & 15)) * PITCH + (lane >> 4) * 16);
    const uint32_t b_off = MATA +
        (uint32_t)((warp_n * 32 + (lane & 7) + ((lane >> 4) << 3)) * PITCH + ((lane >> 3) & 1) * 16);

    float acc[4][4][4];
#pragma unroll
    for (int i = 0; i < 4; i++)
#pragma unroll
        for (int j = 0; j < 4; j++)
#pragma unroll
            for (int e = 0; e < 4; e++) acc[i][j][e] = 0.f;

    uint32_t hacc[4][4][2];
#pragma unroll
    for (int i = 0; i < 4; i++)
#pragma unroll
        for (int j = 0; j < 4; j++) { hacc[i][j][0] = 0u; hacc[i][j][1] = 0u; }

    const int nch = K >> 6;

    load_stage<AMODE>(sbase, t, A, B, row0, col0, K, 0);
    cp_commit();

    uint32_t afr[2][4][4], bfr[2][4][2];

    for (int i = 0; i < nch; i++) {
        cp_wait<0>();
        __syncthreads();

        if (i + 1 < nch)
            load_stage<AMODE>(sbase + ((i + 1) & 1) * STAGEB, t, A, B,
                              row0, col0, K, (i + 1) * 64);
        cp_commit();

        const uint32_t sb = sbase + (uint32_t)(i & 1) * STAGEB;

#pragma unroll
        for (int mt = 0; mt < 4; mt++)
            ldmx4(afr[0][mt], sb + a_off + (uint32_t)(mt * (16 * PITCH)));
#pragma unroll
        for (int j = 0; j < 2; j++) {
            uint32_t r[4];
            ldmx4(r, sb + b_off + (uint32_t)(j * (16 * PITCH)));
            bfr[0][2 * j][0] = r[0]; bfr[0][2 * j][1] = r[1];
            bfr[0][2 * j + 1][0] = r[2]; bfr[0][2 * j + 1][1] = r[3];
        }

#pragma unroll
        for (int kk = 0; kk < 4; kk++) {
            const int cur = kk & 1, nxt = cur ^ 1;
            if (kk < 3) {
#pragma unroll
                for (int mt = 0; mt < 4; mt++)
                    ldmx4(afr[nxt][mt],
                          sb + a_off + (uint32_t)(mt * (16 * PITCH) + (kk + 1) * 32));
#pragma unroll
                for (int j = 0; j < 2; j++) {
                    uint32_t r[4];
                    ldmx4(r, sb + b_off + (uint32_t)(j * (16 * PITCH) + (kk + 1) * 32));
                    bfr[nxt][2 * j][0] = r[0]; bfr[nxt][2 * j][1] = r[1];
                    bfr[nxt][2 * j + 1][0] = r[2]; bfr[nxt][2 * j + 1][1] = r[3];
                }
            }
#pragma unroll
            for (int mt = 0; mt < 4; mt++)
#pragma unroll
                for (int nt = 0; nt < 4; nt++)
                    mma_h(hacc[mt][nt],
                          afr[cur][mt][0], afr[cur][mt][1],
                          afr[cur][mt][2], afr[cur][mt][3],
                          bfr[cur][nt][0], bfr[cur][nt][1]);
        }

        // periodic flush of fp16 accumulators into fp32
        if (((i & (FLUSH - 1)) == (FLUSH - 1)) || (i == nch - 1)) {
#pragma unroll
            for (int mt = 0; mt < 4; mt++)
#pragma unroll
                for (int nt = 0; nt < 4; nt++) {
                    const float2 f0 = __half22float2(*(__half2*)&hacc[mt][nt][0]);
                    const float2 f1 = __half22float2(*(__half2*)&hacc[mt][nt][1]);
                    acc[mt][nt][0] += f0.x;
                    acc[mt][nt][1] += f0.y;
                    acc[mt][nt][2] += f1.x;
                    acc[mt][nt][3] += f1.y;
                    hacc[mt][nt][0] = 0u;
                    hacc[mt][nt][1] = 0u;
                }
        }
    }

    // epilogue
#pragma unroll
    for (int mt = 0; mt < 4; mt++) {
        const int r0 = row0 + warp_m * 64 + mt * 16 + tr;
#pragma unroll
        for (int nt = 0; nt < 4; nt++) {
            const int cc = col0 + warp_n * 32 + nt * 8 + tc * 2;
            const float bx = __ldg(bias + cc), by = __ldg(bias + cc + 1);
            float2 v0 = make_float2(acc[mt][nt][0] + bx, acc[mt][nt][1] + by);
            float2 v1 = make_float2(acc[mt][nt][2] + bx, acc[mt][nt][3] + by);
            float* p0 = C + (size_t)r0 * DIMN + cc;
            float* p1 = C + (size_t)(r0 + 8) * DIMN + cc;
            if (EPI == 3) {
                float2 o0 = *(const float2*)p0;
                float2 o1 = *(const float2*)p1;
                v0.x = o0.x + 0.3f * v0.x;  v0.y = o0.y + 0.3f * v0.y;
                v1.x = o1.x + 0.3f * v1.x;  v1.y = o1.y + 0.3f * v1.y;
            }
            if (EPI != 2) {
                *(float2*)p0 = v0;
                *(float2*)p1 = v1;
            }
            if (EPI == 1 || EPI == 2) {
                __half2 h0, h1;
                h0.x = __float2half(fmaxf(v0.x, 0.f));
                h0.y = __float2half(fmaxf(v0.y, 0.f));
                h1.x = __float2half(fmaxf(v1.x, 0.f));
                h1.y = __float2half(fmaxf(v1.y, 0.f));
                *(__half2*)(H + (size_t)r0 * DIMN + cc)       = h0;
                *(__half2*)(H + (size_t)(r0 + 8) * DIMN + cc) = h1;
            }
        }
    }
}

// ---------------- tail stage A ------------------------------------------------------
__global__ void __launch_bounds__(256) tail_pre(
    const float* __restrict__ alpha_all,
    const float* __restrict__ att_mask,
    const float* __restrict__ ln_g, const float* __restrict__ ln_b,
    __half* __restrict__ sptH, __half* __restrict__ saggH)
{
    const int b    = blockIdx.x;
    const int t    = threadIdx.x;
    const int warp = t >> 5;
    const int lane = t & 31;

    __shared__ float spt [NTOP][DIMN];
    __shared__ float sagg[NTOP][DIMN];
    __shared__ float adj [SEQ][NTOP];
    __shared__ float sums[20];
    __shared__ int   idxs[NTOP];
    __shared__ float smask[SEQ];

    if (t < SEQ) smask[t] = att_mask[b * SEQ + t];
    __syncthreads();

    if (t < 20) {
        float s = 0.f;
        for (int si = 0; si < SEQ; si++)
            s = fmaf(alpha_all[((size_t)b * SEQ + si) * 20 + t], smask[si], s);
        sums[t] = s;
    }
    __syncthreads();

    if (t == 0) {
        unsigned used = 0;
        for (int k = 0; k < NTOP; k++) {
            int best = 0; float bv = -3.4e38f;
            for (int p = 0; p < 20; p++)
                if (!((used >> p) & 1u) && sums[p] > bv) { bv = sums[p]; best = p; }
            used |= (1u << best);
            idxs[k] = best;
        }
    }
    __syncthreads();

    for (int i = t; i < NTOP * DIMN; i += 256) {
        const int k = i >> 9, d = i & 511;
        spt[k][d] = g_psl[((size_t)b * 20 + idxs[k]) * DIMN + d];
    }
    __syncthreads();

    for (int pair = warp; pair < SEQ * NTOP; pair += 8) {
        const int s = pair / NTOP;
        const int k = pair - s * NTOP;
        const float* xr = g_X + ((size_t)b * SEQ + s) * DIMN;
        float acc = 0.f;
        for (int d = lane; d < DIMN; d += 32)
            acc = fmaf(xr[d], spt[k][d], acc);
#pragma unroll
        for (int o = 16; o > 0; o >>= 1)
            acc += __shfl_down_sync(0xffffffffu, acc, o);
        if (lane == 0) {
            const float v = acc * 0.04419417382415922f;
            adj[s][k] = (smask[s] > 0.f) ? v : -9.0e15f;
        }
    }
    __syncthreads();

    if (warp < NTOP) {
        const int k = warp;
        float v = adj[lane][k];
        float m = v;
#pragma unroll
        for (int o = 16; o > 0; o >>= 1)
            m = fmaxf(m, __shfl_xor_sync(0xffffffffu, m, o));
        const float e = expf(v - m);
        float ss = e;
#pragma unroll
        for (int o = 16; o > 0; o >>= 1)
            ss += __shfl_xor_sync(0xffffffffu, ss, o);
        adj[lane][k] = e / ss;
    }
    __syncthreads();

    for (int d = t; d < DIMN; d += 256) {
        float a[NTOP];
#pragma unroll
        for (int k = 0; k < NTOP; k++) a[k] = 0.f;
        for (int s = 0; s < SEQ; s++) {
            const float xv = g_X[((size_t)b * SEQ + s) * DIMN + d];
#pragma unroll
            for (int k = 0; k < NTOP; k++) a[k] = fmaf(xv, adj[s][k], a[k]);
        }
#pragma unroll
        for (int k = 0; k < NTOP; k++) sagg[k][d] = a[k];
    }
    __syncthreads();

    if (warp < NTOP) {
        const int k = warp;
        float sum = 0.f, sq = 0.f;
        for (int d = lane; d < DIMN; d += 32) {
            const float v = sagg[k][d];
            sum += v;
            sq = fmaf(v, v, sq);
        }
#pragma unroll
        for (int o = 16; o > 0; o >>= 1) {
            sum += __shfl_xor_sync(0xffffffffu, sum, o);
            sq  += __shfl_xor_sync(0xffffffffu, sq,  o);
        }
        const float mu  = sum * (1.f / DIMN);
        const float var = sq * (1.f / DIMN) - mu * mu;
        const float inv = rsqrtf(var + 1e-5f);
        for (int d = lane; d < DIMN; d += 32)
            sagg[k][d] = (sagg[k][d] - mu) * inv * ln_g[d] + ln_b[d];
    }
    __syncthreads();

    for (int i = t; i < NTOP * DIMN; i += 256) {
        const int k = i >> 9, d = i & 511;
        const size_t o = ((size_t)(b * NTOP + k)) * DIMN + d;
        sptH [o] = __float2half(spt[k][d]);
        saggH[o] = __float2half(sagg[k][d]);
    }
}

// ---------------- tail stage B -------------------------------------------------------
__global__ void __launch_bounds__(256) tail_post(
    const float* __restrict__ V, const float* __restrict__ S,
    const float* __restrict__ cl_w, const float* __restrict__ cl_b,
    float* __restrict__ out)
{
    const int row  = blockIdx.x * 8 + (threadIdx.x >> 5);
    const int lane = threadIdx.x & 31;
    const float* v = V + (size_t)row * DIMN;
    const float* s = S + (size_t)row * DIMN;
    float acc = 0.f;
#pragma unroll 4
    for (int d = lane; d < DIMN; d += 32)
        acc = fmaf(tanhf(v[d]) * tanhf(s[d]), cl_w[d], acc);
#pragma unroll
    for (int o = 16; o > 0; o >>= 1)
        acc += __shfl_xor_sync(0xffffffffu, acc, o);
    if (lane == 0)
        out[row] = 1.f / (1.f + expf(-(acc + cl_b[0])));
}

// ---------------- launch --------------------------------------------------------------
extern "C" void kernel_launch(void* const* d_in, const int* in_sizes, int n_in,
                              void* d_out, int out_size)
{
    const float* inputs   = (const float*)d_in[0];
    const float* obj      = (const float*)d_in[2];
    const float* motion   = (const float*)d_in[3];
    const float* att_mask = (const float*)d_in[4];
    const float* alpha    = (const float*)d_in[5];
    const float* conv_w   = (const float*)d_in[6];
    const float* conv_b   = (const float*)d_in[7];
    const float* res_w1   = (const float*)d_in[8];
    const float* res_b1   = (const float*)d_in[9];
    const float* res_w2   = (const float*)d_in[10];
    const float* res_b2   = (const float*)d_in[11];
    const float* psl_w    = (const float*)d_in[12];
    const float* psl_b    = (const float*)d_in[13];
    const float* ln_g     = (const float*)d_in[14];
    const float* ln_b     = (const float*)d_in[15];
    const float* sv_w     = (const float*)d_in[16];
    const float* sv_b     = (const float*)d_in[17];
    const float* ss_w     = (const float*)d_in[18];
    const float* ss_b     = (const float*)d_in[19];
    const float* cl_w     = (const float*)d_in[20];
    const float* cl_b     = (const float*)d_in[21];
    float* out = (float*)d_out;

    float *X, *PSL, *V, *Sv;
    __half *Xh, *Y1h, *A, *Ap, *Wc, *W1, *W2, *Wp, *Wv, *Ws, *SptH, *SaggH;
    cudaGetSymbolAddress((void**)&X,    g_X);
    cudaGetSymbolAddress((void**)&Xh,   g_Xh);
    cudaGetSymbolAddress((void**)&Y1h,  g_Y1h);
    cudaGetSymbolAddress((void**)&PSL,  g_psl);
    cudaGetSymbolAddress((void**)&A,    g_A);
    cudaGetSymbolAddress((void**)&Ap,   g_Ap);
    cudaGetSymbolAddress((void**)&Wc,   g_Wc);
    cudaGetSymbolAddress((void**)&W1,   g_W1);
    cudaGetSymbolAddress((void**)&W2,   g_W2);
    cudaGetSymbolAddress((void**)&Wp,   g_Wp);
    cudaGetSymbolAddress((void**)&Wv,   g_Wv);
    cudaGetSymbolAddress((void**)&Ws,   g_Ws);
    cudaGetSymbolAddress((void**)&SptH, g_SptH);
    cudaGetSymbolAddress((void**)&SaggH,g_SaggH);
    cudaGetSymbolAddress((void**)&V,    g_V);
    cudaGetSymbolAddress((void**)&Sv,   g_Sv);

    const int SMEM_BYTES = 2 * (int)STAGEB;   // 55296
    cudaFuncSetAttribute(gemm_mma<0,1>, cudaFuncAttributeMaxDynamicSharedMemorySize, SMEM_BYTES);
    cudaFuncSetAttribute(gemm_mma<1,2>, cudaFuncAttributeMaxDynamicSharedMemorySize, SMEM_BYTES);
    cudaFuncSetAttribute(gemm_mma<1,3>, cudaFuncAttributeMaxDynamicSharedMemorySize, SMEM_BYTES);
    cudaFuncSetAttribute(gemm_mma<0,0>, cudaFuncAttributeMaxDynamicSharedMemorySize, SMEM_BYTES);

    const dim3 blk(128);
    const dim3 gBig (DIMN / TILEN, 32);   // 256 CTAs
    const dim3 gPsl (DIMN / TILEN, 20);   // 160 CTAs
    const dim3 gTail(DIMN / TILEN, 6);    //  48 CTAs

    // #0: all conversions
    mega_convert<<<1184, 256>>>(inputs, conv_w, res_w1, res_w2, psl_w,
                                obj, motion, sv_w, ss_w,
                                A, Wc, W1, W2, Wp, Ap, Wv, Ws);

    // #1..#3: main GEMM chain
    gemm_mma<0, 1><<<gBig, blk, SMEM_BYTES>>>(A,   Wc, conv_b, X, Xh,  KBIGP);
    gemm_mma<1, 2><<<gBig, blk, SMEM_BYTES>>>(Xh,  W1, res_b1, X, Y1h, KCONV);
    gemm_mma<1, 3><<<gBig, blk, SMEM_BYTES>>>(Y1h, W2, res_b2, X, Xh,  KCONV);

    // #4: proposal GEMM
    gemm_mma<0, 0><<<gPsl, blk, SMEM_BYTES>>>(Ap, Wp, psl_b, PSL, Xh /*unused*/, KPSL);

    // #5: per-batch attention/topk/LN
    tail_pre<<<BS_, 256>>>(alpha, att_mask, ln_g, ln_b, SptH, SaggH);

    // #6/#7: tail GEMMs
    gemm_mma<0, 0><<<gTail, blk, SMEM_BYTES>>>(SptH,  Wv, sv_b, V,  Xh /*unused*/, DIMN);
    gemm_mma<0, 0><<<gTail, blk, SMEM_BYTES>>>(SaggH, Ws, ss_b, Sv, Xh /*unused*/, DIMN);

    // #8: scoring
    tail_post<<<96, 256>>>(V, Sv, cl_w, cl_b, out);
}

// round 15
// speedup vs baseline: 1.5575x; 1.5575x over previous
#include <cuda_runtime.h>
#include <cuda_fp16.h>
#include <math.h>
#include <stdint.h>

#define BS_    128
#define SEQ    32
#define DIMN   512
#define P_     10
#define NTOP   6

#define KBIG   10000
#define KBIGP  10048
#define KCONV  2560
#define KPSL   1024

// ---------------- device scratch ------------------------------------------------
__device__ float  g_X  [BS_ * SEQ * DIMN];
__device__ __half g_Xh [BS_ * SEQ * DIMN];
__device__ __half g_Y1h[BS_ * SEQ * DIMN];
__device__ float  g_psl[BS_ * 2 * P_ * DIMN];

__device__ __half g_A  [(size_t)4096 * KBIGP];
__device__ __half g_Ap [2560 * KPSL];
__device__ __half g_Wc [(size_t)512 * KBIGP];
__device__ __half g_W1 [512 * KCONV];
__device__ __half g_W2 [512 * KCONV];
__device__ __half g_Wp [512 * KPSL];
__device__ __half g_Wv [512 * DIMN];
__device__ __half g_Ws [512 * DIMN];

__device__ __half g_SptH [BS_ * NTOP * DIMN];
__device__ __half g_SaggH[BS_ * NTOP * DIMN];
__device__ float  g_V  [BS_ * NTOP * DIMN];
__device__ float  g_Sv [BS_ * NTOP * DIMN];

// ---------------- ptx helpers -----------------------------------------------------
__device__ __forceinline__ void cp16(uint32_t sa, const void* g) {
    asm volatile("cp.async.cg.shared.global [%0], [%1], 16;\n" :: "r"(sa), "l"(g) : "memory");
}
__device__ __forceinline__ void cp16z(uint32_t sa, const void* g, uint32_t srcsize) {
    asm volatile("cp.async.cg.shared.global [%0], [%1], 16, %2;\n"
                 :: "r"(sa), "l"(g), "r"(srcsize) : "memory");
}
__device__ __forceinline__ void cp_commit() {
    asm volatile("cp.async.commit_group;\n" ::: "memory");
}
template<int N> __device__ __forceinline__ void cp_wait() {
    asm volatile("cp.async.wait_group %0;\n" :: "n"(N) : "memory");
}
__device__ __forceinline__ uint32_t smem_u32(const void* p) {
    uint32_t a;
    asm("{ .reg .u64 t; cvta.to.shared.u64 t, %1; cvt.u32.u64 %0, t; }" : "=r"(a) : "l"(p));
    return a;
}
__device__ __forceinline__ void ldmx4(uint32_t* r, uint32_t addr) {
    asm volatile("ldmatrix.sync.aligned.m8n8.x4.shared.b16 {%0,%1,%2,%3}, [%4];"
                 : "=r"(r[0]), "=r"(r[1]), "=r"(r[2]), "=r"(r[3]) : "r"(addr));
}
__device__ __forceinline__ void mma_f16(float* d,
    uint32_t a0, uint32_t a1, uint32_t a2, uint32_t a3,
    uint32_t b0, uint32_t b1)
{
    asm volatile(
        "mma.sync.aligned.m16n8k16.row.col.f32.f16.f16.f32 "
        "{%0,%1,%2,%3}, {%4,%5,%6,%7}, {%8,%9}, {%0,%1,%2,%3};"
        : "+f"(d[0]), "+f"(d[1]), "+f"(d[2]), "+f"(d[3])
        : "r"(a0), "r"(a1), "r"(a2), "r"(a3), "r"(b0), "r"(b1));
}
__device__ __forceinline__ void cvt8(__half* h, const float* s) {
    const float4 v0 = *(const float4*)s;
    const float4 v1 = *(const float4*)(s + 4);
    h[0] = __float2half(v0.x); h[1] = __float2half(v0.y);
    h[2] = __float2half(v0.z); h[3] = __float2half(v0.w);
    h[4] = __float2half(v1.x); h[5] = __float2half(v1.y);
    h[6] = __float2half(v1.z); h[7] = __float2half(v1.w);
}

// ---------------- mega conversion kernel -------------------------------------------
#define CPR_BIG  (KBIGP / 8)
#define S0N (4096 * CPR_BIG)
#define S1N (512 * CPR_BIG)
#define S2N (512 * (KCONV / 8))
#define S3N S2N
#define S4N (512 * (KPSL / 8))
#define S5N (2560 * (KPSL / 8))
#define S6N (512 * (DIMN / 8))
#define S7N S6N
#define E0 S0N
#define E1 (E0 + S1N)
#define E2 (E1 + S2N)
#define E3 (E2 + S3N)
#define E4 (E3 + S4N)
#define E5 (E4 + S5N)
#define E6 (E5 + S6N)
#define E7 (E6 + S7N)

__global__ void __launch_bounds__(256) mega_convert(
    const float* __restrict__ inputs, const float* __restrict__ conv_w,
    const float* __restrict__ res_w1, const float* __restrict__ res_w2,
    const float* __restrict__ psl_w,
    const float* __restrict__ obj, const float* __restrict__ motion,
    const float* __restrict__ sv_w, const float* __restrict__ ss_w,
    __half* __restrict__ A, __half* __restrict__ Wc,
    __half* __restrict__ W1, __half* __restrict__ W2,
    __half* __restrict__ Wp, __half* __restrict__ Ap,
    __half* __restrict__ Wv, __half* __restrict__ Ws)
{
    const int stride = gridDim.x * blockDim.x;
    for (int i = blockIdx.x * blockDim.x + threadIdx.x; i < E7; i += stride) {
        __half h[8];
        if (i < E0) {
            const int row = i / CPR_BIG, ch = i - row * CPR_BIG;
            const int c8 = ch << 3;
            if (c8 < KBIG) cvt8(h, inputs + (size_t)row * KBIG + c8);
            else { h[0]=h[1]=h[2]=h[3]=h[4]=h[5]=h[6]=h[7]=__float2half(0.f); }
            *(uint4*)(A + (size_t)row * KBIGP + c8) = *(const uint4*)h;
        } else if (i < E1) {
            const int j = i - E0;
            const int row = j / CPR_BIG, ch = j - row * CPR_BIG;
            const int c8 = ch << 3;
            if (c8 < KBIG) cvt8(h, conv_w + (size_t)row * KBIG + c8);
            else { h[0]=h[1]=h[2]=h[3]=h[4]=h[5]=h[6]=h[7]=__float2half(0.f); }
            *(uint4*)(Wc + (size_t)row * KBIGP + c8) = *(const uint4*)h;
        } else if (i < E3) {
            const int j = (i < E2) ? (i - E1) : (i - E2);
            const float* src = (i < E2) ? res_w1 : res_w2;
            __half* dst = (i < E2) ? W1 : W2;
            const int dout = j / 320, ch = j - dout * 320;
            const int k0 = ch << 3;
            const int tap = k0 >> 9, din0 = k0 & 511;
            const float* s = src + dout * KCONV + din0 * 5 + tap;
#pragma unroll
            for (int e = 0; e < 8; e++) h[e] = __float2half(s[e * 5]);
            *(uint4*)(dst + dout * KCONV + k0) = *(const uint4*)h;
        } else if (i < E4) {
            const int j = i - E3;
            const int row = j >> 7, c8 = (j & 127) << 3;
            cvt8(h, psl_w + (size_t)row * KPSL + c8);
            *(uint4*)(Wp + (size_t)row * KPSL + c8) = *(const uint4*)h;
        } else if (i < E5) {
            const int j = i - E4;
            const int row = j >> 7, c8 = (j & 127) << 3;
            const int b = row / 20, p = row - b * 20;
            const float* s = (p < P_) ? obj    + ((size_t)(b * P_ + p      )) * KPSL + c8
                                      : motion + ((size_t)(b * P_ + p - P_ )) * KPSL + c8;
            cvt8(h, s);
            *(uint4*)(Ap + (size_t)row * KPSL + c8) = *(const uint4*)h;
        } else if (i < E6) {
            const int j = i - E5;
            const int row = j >> 6, c8 = (j & 63) << 3;
            cvt8(h, sv_w + (size_t)row * DIMN + c8);
            *(uint4*)(Wv + (size_t)row * DIMN + c8) = *(const uint4*)h;
        } else {
            const int j = i - E6;
            const int row = j >> 6, c8 = (j & 63) << 3;
            cvt8(h, ss_w + (size_t)row * DIMN + c8);
            *(uint4*)(Ws + (size_t)row * DIMN + c8) = *(const uint4*)h;
        }
    }
}

// ---------------- mma.sync GEMM (R11/R12 champion, fp32 accumulators) --------------
#define TILEN   64
#define PITCH   144u
#define MATA    (128u * PITCH)
#define STAGEB  (MATA + 64u * PITCH)

template<int AMODE>
__device__ __forceinline__ void load_stage(
    uint32_t sb, int t,
    const __half* __restrict__ A, const __half* __restrict__ B,
    int row0, int col0, int K, int k0)
{
#pragma unroll
    for (int j = 0; j < 8; j++) {
        const int cid = j * 128 + t;
        const int r  = cid >> 3, ch = cid & 7;
        const uint32_t sa = sb + (uint32_t)(r * PITCH + ch * 16);
        if (AMODE == 0) {
            cp16(sa, A + (size_t)(row0 + r) * K + k0 + ch * 8);
        } else {
            const int grow = row0 + r;
            const int tap  = k0 >> 9;
            const int din0 = (k0 & 511) + ch * 8;
            const int s2   = (grow & 31) + tap - 2;
            const uint32_t ok = (s2 >= 0 && s2 < SEQ) ? 16u : 0u;
            const int srow = ok ? (grow + tap - 2) : grow;
            cp16z(sa, A + (size_t)srow * DIMN + din0, ok);
        }
    }
#pragma unroll
    for (int j = 0; j < 4; j++) {
        const int cid = j * 128 + t;
        const int r  = cid >> 3, ch = cid & 7;
        cp16(sb + MATA + (uint32_t)(r * PITCH + ch * 16),
             B + (size_t)(col0 + r) * K + k0 + ch * 8);
    }
}

// EPI 0: C=acc+b | 1: C=acc+b, H=h(relu) | 2: H only | 3: C += 0.3*(acc+b)
// EPI 5: fused tail pair — blockIdx.z selects (A,B,bias,C) operand set.
template<int AMODE, int EPI>
__global__ void __launch_bounds__(128, 3) gemm_mma(
    const __half* __restrict__ A, const __half* __restrict__ B,
    const float* __restrict__ bias, float* __restrict__ C,
    __half* __restrict__ H, int K,
    const __half* A2 = nullptr, const __half* B2 = nullptr,
    const float* bias2 = nullptr, float* C2 = nullptr)
{
    extern __shared__ char smem[];
    const uint32_t sbase = smem_u32(smem);
    const int t = threadIdx.x;
    const int wid = t >> 5, lane = t & 31;
    const int warp_m = wid >> 1, warp_n = wid & 1;
    const int tr = lane >> 2, tc = lane & 3;
    const int row0 = blockIdx.y * 128;
    const int col0 = blockIdx.x * TILEN;

    if (EPI == 5 && blockIdx.z == 1) { A = A2; B = B2; bias = bias2; C = C2; }

    const uint32_t a_off = (uint32_t)((warp_m * 64 + (lane & 15)) * PITCH + (lane >> 4) * 16);
    const uint32_t b_off = MATA +
        (uint32_t)((warp_n * 32 + (lane & 7) + ((lane >> 4) << 3)) * PITCH + ((lane >> 3) & 1) * 16);

    float acc[4][4][4];
#pragma unroll
    for (int i = 0; i < 4; i++)
#pragma unroll
        for (int j = 0; j < 4; j++)
#pragma unroll
            for (int e = 0; e < 4; e++) acc[i][j][e] = 0.f;

    const int nch = K >> 6;

    load_stage<AMODE>(sbase, t, A, B, row0, col0, K, 0);
    cp_commit();

    uint32_t afr[2][4][4], bfr[2][4][2];

    for (int i = 0; i < nch; i++) {
        cp_wait<0>();
        __syncthreads();

        if (i + 1 < nch)
            load_stage<AMODE>(sbase + ((i + 1) & 1) * STAGEB, t, A, B,
                              row0, col0, K, (i + 1) * 64);
        cp_commit();

        const uint32_t sb = sbase + (uint32_t)(i & 1) * STAGEB;

#pragma unroll
        for (int mt = 0; mt < 4; mt++)
            ldmx4(afr[0][mt], sb + a_off + (uint32_t)(mt * (16 * PITCH)));
#pragma unroll
        for (int j = 0; j < 2; j++) {
            uint32_t r[4];
            ldmx4(r, sb + b_off + (uint32_t)(j * (16 * PITCH)));
            bfr[0][2 * j][0] = r[0]; bfr[0][2 * j][1] = r[1];
            bfr[0][2 * j + 1][0] = r[2]; bfr[0][2 * j + 1][1] = r[3];
        }

#pragma unroll
        for (int kk = 0; kk < 4; kk++) {
            const int cur = kk & 1, nxt = cur ^ 1;
            if (kk < 3) {
#pragma unroll
                for (int mt = 0; mt < 4; mt++)
                    ldmx4(afr[nxt][mt],
                          sb + a_off + (uint32_t)(mt * (16 * PITCH) + (kk + 1) * 32));
#pragma unroll
                for (int j = 0; j < 2; j++) {
                    uint32_t r[4];
                    ldmx4(r, sb + b_off + (uint32_t)(j * (16 * PITCH) + (kk + 1) * 32));
                    bfr[nxt][2 * j][0] = r[0]; bfr[nxt][2 * j][1] = r[1];
                    bfr[nxt][2 * j + 1][0] = r[2]; bfr[nxt][2 * j + 1][1] = r[3];
                }
            }
#pragma unroll
            for (int mt = 0; mt < 4; mt++)
#pragma unroll
                for (int nt = 0; nt < 4; nt++)
                    mma_f16(acc[mt][nt],
                            afr[cur][mt][0], afr[cur][mt][1],
                            afr[cur][mt][2], afr[cur][mt][3],
                            bfr[cur][nt][0], bfr[cur][nt][1]);
        }
    }

    // epilogue
#pragma unroll
    for (int mt = 0; mt < 4; mt++) {
        const int r0 = row0 + warp_m * 64 + mt * 16 + tr;
#pragma unroll
        for (int nt = 0; nt < 4; nt++) {
            const int cc = col0 + warp_n * 32 + nt * 8 + tc * 2;
            const float bx = __ldg(bias + cc), by = __ldg(bias + cc + 1);
            float2 v0 = make_float2(acc[mt][nt][0] + bx, acc[mt][nt][1] + by);
            float2 v1 = make_float2(acc[mt][nt][2] + bx, acc[mt][nt][3] + by);
            float* p0 = C + (size_t)r0 * DIMN + cc;
            float* p1 = C + (size_t)(r0 + 8) * DIMN + cc;
            if (EPI == 3) {
                float2 o0 = *(const float2*)p0;
                float2 o1 = *(const float2*)p1;
                v0.x = o0.x + 0.3f * v0.x;  v0.y = o0.y + 0.3f * v0.y;
                v1.x = o1.x + 0.3f * v1.x;  v1.y = o1.y + 0.3f * v1.y;
            }
            if (EPI != 2) {
                *(float2*)p0 = v0;
                *(float2*)p1 = v1;
            }
            if (EPI == 1 || EPI == 2) {
                __half2 h0, h1;
                h0.x = __float2half(fmaxf(v0.x, 0.f));
                h0.y = __float2half(fmaxf(v0.y, 0.f));
                h1.x = __float2half(fmaxf(v1.x, 0.f));
                h1.y = __float2half(fmaxf(v1.y, 0.f));
                *(__half2*)(H + (size_t)r0 * DIMN + cc)       = h0;
                *(__half2*)(H + (size_t)(r0 + 8) * DIMN + cc) = h1;
            }
        }
    }
}

// ---------------- tail stage A ------------------------------------------------------
__global__ void __launch_bounds__(256) tail_pre(
    const float* __restrict__ alpha_all,
    const float* __restrict__ att_mask,
    const float* __restrict__ ln_g, const float* __restrict__ ln_b,
    __half* __restrict__ sptH, __half* __restrict__ saggH)
{
    const int b    = blockIdx.x;
    const int t    = threadIdx.x;
    const int warp = t >> 5;
    const int lane = t & 31;

    __shared__ float spt [NTOP][DIMN];
    __shared__ float sagg[NTOP][DIMN];
    __shared__ float adj [SEQ][NTOP];
    __shared__ float sums[20];
    __shared__ int   idxs[NTOP];
    __shared__ float smask[SEQ];

    if (t < SEQ) smask[t] = att_mask[b * SEQ + t];
    __syncthreads();

    if (t < 20) {
        float s = 0.f;
        for (int si = 0; si < SEQ; si++)
            s = fmaf(alpha_all[((size_t)b * SEQ + si) * 20 + t], smask[si], s);
        sums[t] = s;
    }
    __syncthreads();

    if (t == 0) {
        unsigned used = 0;
        for (int k = 0; k < NTOP; k++) {
            int best = 0; float bv = -3.4e38f;
            for (int p = 0; p < 20; p++)
                if (!((used >> p) & 1u) && sums[p] > bv) { bv = sums[p]; best = p; }
            used |= (1u << best);
            idxs[k] = best;
        }
    }
    __syncthreads();

    for (int i = t; i < NTOP * DIMN; i += 256) {
        const int k = i >> 9, d = i & 511;
        spt[k][d] = g_psl[((size_t)b * 20 + idxs[k]) * DIMN + d];
    }
    __syncthreads();

    for (int pair = warp; pair < SEQ * NTOP; pair += 8) {
        const int s = pair / NTOP;
        const int k = pair - s * NTOP;
        const float* xr = g_X + ((size_t)b * SEQ + s) * DIMN;
        float acc = 0.f;
        for (int d = lane; d < DIMN; d += 32)
            acc = fmaf(xr[d], spt[k][d], acc);
#pragma unroll
        for (int o = 16; o > 0; o >>= 1)
            acc += __shfl_down_sync(0xffffffffu, acc, o);
        if (lane == 0) {
            const float v = acc * 0.04419417382415922f;
            adj[s][k] = (smask[s] > 0.f) ? v : -9.0e15f;
        }
    }
    __syncthreads();

    if (warp < NTOP) {
        const int k = warp;
        float v = adj[lane][k];
        float m = v;
#pragma unroll
        for (int o = 16; o > 0; o >>= 1)
            m = fmaxf(m, __shfl_xor_sync(0xffffffffu, m, o));
        const float e = expf(v - m);
        float ss = e;
#pragma unroll
        for (int o = 16; o > 0; o >>= 1)
            ss += __shfl_xor_sync(0xffffffffu, ss, o);
        adj[lane][k] = e / ss;
    }
    __syncthreads();

    for (int d = t; d < DIMN; d += 256) {
        float a[NTOP];
#pragma unroll
        for (int k = 0; k < NTOP; k++) a[k] = 0.f;
        for (int s = 0; s < SEQ; s++) {
            const float xv = g_X[((size_t)b * SEQ + s) * DIMN + d];
#pragma unroll
            for (int k = 0; k < NTOP; k++) a[k] = fmaf(xv, adj[s][k], a[k]);
        }
#pragma unroll
        for (int k = 0; k < NTOP; k++) sagg[k][d] = a[k];
    }
    __syncthreads();

    if (warp < NTOP) {
        const int k = warp;
        float sum = 0.f, sq = 0.f;
        for (int d = lane; d < DIMN; d += 32) {
            const float v = sagg[k][d];
            sum += v;
            sq = fmaf(v, v, sq);
        }
#pragma unroll
        for (int o = 16; o > 0; o >>= 1) {
            sum += __shfl_xor_sync(0xffffffffu, sum, o);
            sq  += __shfl_xor_sync(0xffffffffu, sq,  o);
        }
        const float mu  = sum * (1.f / DIMN);
        const float var = sq * (1.f / DIMN) - mu * mu;
        const float inv = rsqrtf(var + 1e-5f);
        for (int d = lane; d < DIMN; d += 32)
            sagg[k][d] = (sagg[k][d] - mu) * inv * ln_g[d] + ln_b[d];
    }
    __syncthreads();

    for (int i = t; i < NTOP * DIMN; i += 256) {
        const int k = i >> 9, d = i & 511;
        const size_t o = ((size_t)(b * NTOP + k)) * DIMN + d;
        sptH [o] = __float2half(spt[k][d]);
        saggH[o] = __float2half(sagg[k][d]);
    }
}

// ---------------- tail stage B -------------------------------------------------------
__global__ void __launch_bounds__(256) tail_post(
    const float* __restrict__ V, const float* __restrict__ S,
    const float* __restrict__ cl_w, const float* __restrict__ cl_b,
    float* __restrict__ out)
{
    const int row  = blockIdx.x * 8 + (threadIdx.x >> 5);
    const int lane = threadIdx.x & 31;
    const float* v = V + (size_t)row * DIMN;
    const float* s = S + (size_t)row * DIMN;
    float acc = 0.f;
#pragma unroll 4
    for (int d = lane; d < DIMN; d += 32)
        acc = fmaf(tanhf(v[d]) * tanhf(s[d]), cl_w[d], acc);
#pragma unroll
    for (int o = 16; o > 0; o >>= 1)
        acc += __shfl_xor_sync(0xffffffffu, acc, o);
    if (lane == 0)
        out[row] = 1.f / (1.f + expf(-(acc + cl_b[0])));
}

// ---------------- launch --------------------------------------------------------------
extern "C" void kernel_launch(void* const* d_in, const int* in_sizes, int n_in,
                              void* d_out, int out_size)
{
    const float* inputs   = (const float*)d_in[0];
    const float* obj      = (const float*)d_in[2];
    const float* motion   = (const float*)d_in[3];
    const float* att_mask = (const float*)d_in[4];
    const float* alpha    = (const float*)d_in[5];
    const float* conv_w   = (const float*)d_in[6];
    const float* conv_b   = (const float*)d_in[7];
    const float* res_w1   = (const float*)d_in[8];
    const float* res_b1   = (const float*)d_in[9];
    const float* res_w2   = (const float*)d_in[10];
    const float* res_b2   = (const float*)d_in[11];
    const float* psl_w    = (const float*)d_in[12];
    const float* psl_b    = (const float*)d_in[13];
    const float* ln_g     = (const float*)d_in[14];
    const float* ln_b     = (const float*)d_in[15];
    const float* sv_w     = (const float*)d_in[16];
    const float* sv_b     = (const float*)d_in[17];
    const float* ss_w     = (const float*)d_in[18];
    const float* ss_b     = (const float*)d_in[19];
    const float* cl_w     = (const float*)d_in[20];
    const float* cl_b     = (const float*)d_in[21];
    float* out = (float*)d_out;

    float *X, *PSL, *V, *Sv;
    __half *Xh, *Y1h, *A, *Ap, *Wc, *W1, *W2, *Wp, *Wv, *Ws, *SptH, *SaggH;
    cudaGetSymbolAddress((void**)&X,    g_X);
    cudaGetSymbolAddress((void**)&Xh,   g_Xh);
    cudaGetSymbolAddress((void**)&Y1h,  g_Y1h);
    cudaGetSymbolAddress((void**)&PSL,  g_psl);
    cudaGetSymbolAddress((void**)&A,    g_A);
    cudaGetSymbolAddress((void**)&Ap,   g_Ap);
    cudaGetSymbolAddress((void**)&Wc,   g_Wc);
    cudaGetSymbolAddress((void**)&W1,   g_W1);
    cudaGetSymbolAddress((void**)&W2,   g_W2);
    cudaGetSymbolAddress((void**)&Wp,   g_Wp);
    cudaGetSymbolAddress((void**)&Wv,   g_Wv);
    cudaGetSymbolAddress((void**)&Ws,   g_Ws);
    cudaGetSymbolAddress((void**)&SptH, g_SptH);
    cudaGetSymbolAddress((void**)&SaggH,g_SaggH);
    cudaGetSymbolAddress((void**)&V,    g_V);
    cudaGetSymbolAddress((void**)&Sv,   g_Sv);

    const int SMEM_BYTES = 2 * (int)STAGEB;   // 55296
    cudaFuncSetAttribute(gemm_mma<0,1>, cudaFuncAttributeMaxDynamicSharedMemorySize, SMEM_BYTES);
    cudaFuncSetAttribute(gemm_mma<1,2>, cudaFuncAttributeMaxDynamicSharedMemorySize, SMEM_BYTES);
    cudaFuncSetAttribute(gemm_mma<1,3>, cudaFuncAttributeMaxDynamicSharedMemorySize, SMEM_BYTES);
    cudaFuncSetAttribute(gemm_mma<0,0>, cudaFuncAttributeMaxDynamicSharedMemorySize, SMEM_BYTES);
    cudaFuncSetAttribute(gemm_mma<0,5>, cudaFuncAttributeMaxDynamicSharedMemorySize, SMEM_BYTES);

    const dim3 blk(128);
    const dim3 gBig (DIMN / TILEN, 32);      // 256 CTAs
    const dim3 gPsl (DIMN / TILEN, 20);      // 160 CTAs
    const dim3 gTail(DIMN / TILEN, 6, 2);    //  96 CTAs (both tail GEMMs fused)

    // #0: all conversions
    mega_convert<<<1184, 256>>>(inputs, conv_w, res_w1, res_w2, psl_w,
                                obj, motion, sv_w, ss_w,
                                A, Wc, W1, W2, Wp, Ap, Wv, Ws);

    // #1..#3: main GEMM chain
    gemm_mma<0, 1><<<gBig, blk, SMEM_BYTES>>>(A,   Wc, conv_b, X, Xh,  KBIGP);
    gemm_mma<1, 2><<<gBig, blk, SMEM_BYTES>>>(Xh,  W1, res_b1, X, Y1h, KCONV);
    gemm_mma<1, 3><<<gBig, blk, SMEM_BYTES>>>(Y1h, W2, res_b2, X, Xh,  KCONV);

    // #4: proposal GEMM
    gemm_mma<0, 0><<<gPsl, blk, SMEM_BYTES>>>(Ap, Wp, psl_b, PSL, Xh /*unused*/, KPSL);

    // #5: per-batch attention/topk/LN
    tail_pre<<<BS_, 256>>>(alpha, att_mask, ln_g, ln_b, SptH, SaggH);

    // #6: both tail GEMMs in one launch (z selects operand set)
    gemm_mma<0, 5><<<gTail, blk, SMEM_BYTES>>>(SptH, Wv, sv_b, V, Xh /*unused*/, DIMN,
                                               SaggH, Ws, ss_b, Sv);

    // #7: scoring
    tail_post<<<96, 256>>>(V, Sv, cl_w, cl_b, out);
}

// round 17
// speedup vs baseline: 1.6089x; 1.0330x over previous
#include <cuda_runtime.h>
#include <cuda_fp16.h>
#include <math.h>
#include <stdint.h>

#define BS_    128
#define SEQ    32
#define DIMN   512
#define P_     10
#define NTOP   6

#define KBIG   10000
#define KBIGP  10048
#define KCONV  2560
#define KPSL   1024

// ---------------- device scratch ------------------------------------------------
__device__ float  g_X  [BS_ * SEQ * DIMN];
__device__ __half g_Xh [BS_ * SEQ * DIMN];
__device__ __half g_Y1h[BS_ * SEQ * DIMN];
__device__ float  g_psl[BS_ * 2 * P_ * DIMN];

__device__ __half g_A  [(size_t)4096 * KBIGP];
__device__ __half g_Ap [2560 * KPSL];
__device__ __half g_Wc [(size_t)512 * KBIGP];
__device__ __half g_W1 [512 * KCONV];
__device__ __half g_W2 [512 * KCONV];
__device__ __half g_Wp [512 * KPSL];
__device__ __half g_Wv [512 * DIMN];
__device__ __half g_Ws [512 * DIMN];

__device__ __half g_SptH [BS_ * NTOP * DIMN];
__device__ __half g_SaggH[BS_ * NTOP * DIMN];
__device__ float  g_V  [BS_ * NTOP * DIMN];
__device__ float  g_Sv [BS_ * NTOP * DIMN];

// ---------------- ptx helpers -----------------------------------------------------
__device__ __forceinline__ void cp16(uint32_t sa, const void* g) {
    asm volatile("cp.async.cg.shared.global [%0], [%1], 16;\n" :: "r"(sa), "l"(g) : "memory");
}
__device__ __forceinline__ void cp16z(uint32_t sa, const void* g, uint32_t srcsize) {
    asm volatile("cp.async.cg.shared.global [%0], [%1], 16, %2;\n"
                 :: "r"(sa), "l"(g), "r"(srcsize) : "memory");
}
__device__ __forceinline__ void cp_commit() {
    asm volatile("cp.async.commit_group;\n" ::: "memory");
}
template<int N> __device__ __forceinline__ void cp_wait() {
    asm volatile("cp.async.wait_group %0;\n" :: "n"(N) : "memory");
}
__device__ __forceinline__ uint32_t smem_u32(const void* p) {
    uint32_t a;
    asm("{ .reg .u64 t; cvta.to.shared.u64 t, %1; cvt.u32.u64 %0, t; }" : "=r"(a) : "l"(p));
    return a;
}
__device__ __forceinline__ void ldmx4(uint32_t* r, uint32_t addr) {
    asm volatile("ldmatrix.sync.aligned.m8n8.x4.shared.b16 {%0,%1,%2,%3}, [%4];"
                 : "=r"(r[0]), "=r"(r[1]), "=r"(r[2]), "=r"(r[3]) : "r"(addr));
}
__device__ __forceinline__ void mma_f16(float* d,
    uint32_t a0, uint32_t a1, uint32_t a2, uint32_t a3,
    uint32_t b0, uint32_t b1)
{
    asm volatile(
        "mma.sync.aligned.m16n8k16.row.col.f32.f16.f16.f32 "
        "{%0,%1,%2,%3}, {%4,%5,%6,%7}, {%8,%9}, {%0,%1,%2,%3};"
        : "+f"(d[0]), "+f"(d[1]), "+f"(d[2]), "+f"(d[3])
        : "r"(a0), "r"(a1), "r"(a2), "r"(a3), "r"(b0), "r"(b1));
}
__device__ __forceinline__ void cvt8(__half* h, const float* s) {
    const float4 v0 = *(const float4*)s;
    const float4 v1 = *(const float4*)(s + 4);
    h[0] = __float2half(v0.x); h[1] = __float2half(v0.y);
    h[2] = __float2half(v0.z); h[3] = __float2half(v0.w);
    h[4] = __float2half(v1.x); h[5] = __float2half(v1.y);
    h[6] = __float2half(v1.z); h[7] = __float2half(v1.w);
}

// ---------------- mega conversion kernel -------------------------------------------
#define CPR_BIG  (KBIGP / 8)
#define S0N (4096 * CPR_BIG)
#define S1N (512 * CPR_BIG)
#define S2N (512 * (KCONV / 8))
#define S3N S2N
#define S4N (512 * (KPSL / 8))
#define S5N (2560 * (KPSL / 8))
#define S6N (512 * (DIMN / 8))
#define S7N S6N
#define E0 S0N
#define E1 (E0 + S1N)
#define E2 (E1 + S2N)
#define E3 (E2 + S3N)
#define E4 (E3 + S4N)
#define E5 (E4 + S5N)
#define E6 (E5 + S6N)
#define E7 (E6 + S7N)

__global__ void __launch_bounds__(256) mega_convert(
    const float* __restrict__ inputs, const float* __restrict__ conv_w,
    const float* __restrict__ res_w1, const float* __restrict__ res_w2,
    const float* __restrict__ psl_w,
    const float* __restrict__ obj, const float* __restrict__ motion,
    const float* __restrict__ sv_w, const float* __restrict__ ss_w,
    __half* __restrict__ A, __half* __restrict__ Wc,
    __half* __restrict__ W1, __half* __restrict__ W2,
    __half* __restrict__ Wp, __half* __restrict__ Ap,
    __half* __restrict__ Wv, __half* __restrict__ Ws)
{
    const int stride = gridDim.x * blockDim.x;
    for (int i = blockIdx.x * blockDim.x + threadIdx.x; i < E7; i += stride) {
        __half h[8];
        if (i < E0) {
            const int row = i / CPR_BIG, ch = i - row * CPR_BIG;
            const int c8 = ch << 3;
            if (c8 < KBIG) cvt8(h, inputs + (size_t)row * KBIG + c8);
            else { h[0]=h[1]=h[2]=h[3]=h[4]=h[5]=h[6]=h[7]=__float2half(0.f); }
            *(uint4*)(A + (size_t)row * KBIGP + c8) = *(const uint4*)h;
        } else if (i < E1) {
            const int j = i - E0;
            const int row = j / CPR_BIG, ch = j - row * CPR_BIG;
            const int c8 = ch << 3;
            if (c8 < KBIG) cvt8(h, conv_w + (size_t)row * KBIG + c8);
            else { h[0]=h[1]=h[2]=h[3]=h[4]=h[5]=h[6]=h[7]=__float2half(0.f); }
            *(uint4*)(Wc + (size_t)row * KBIGP + c8) = *(const uint4*)h;
        } else if (i < E3) {
            const int j = (i < E2) ? (i - E1) : (i - E2);
            const float* src = (i < E2) ? res_w1 : res_w2;
            __half* dst = (i < E2) ? W1 : W2;
            const int dout = j / 320, ch = j - dout * 320;
            const int k0 = ch << 3;
            const int tap = k0 >> 9, din0 = k0 & 511;
            const float* s = src + dout * KCONV + din0 * 5 + tap;
#pragma unroll
            for (int e = 0; e < 8; e++) h[e] = __float2half(s[e * 5]);
            *(uint4*)(dst + dout * KCONV + k0) = *(const uint4*)h;
        } else if (i < E4) {
            const int j = i - E3;
            const int row = j >> 7, c8 = (j & 127) << 3;
            cvt8(h, psl_w + (size_t)row * KPSL + c8);
            *(uint4*)(Wp + (size_t)row * KPSL + c8) = *(const uint4*)h;
        } else if (i < E5) {
            const int j = i - E4;
            const int row = j >> 7, c8 = (j & 127) << 3;
            const int b = row / 20, p = row - b * 20;
            const float* s = (p < P_) ? obj    + ((size_t)(b * P_ + p      )) * KPSL + c8
                                      : motion + ((size_t)(b * P_ + p - P_ )) * KPSL + c8;
            cvt8(h, s);
            *(uint4*)(Ap + (size_t)row * KPSL + c8) = *(const uint4*)h;
        } else if (i < E6) {
            const int j = i - E5;
            const int row = j >> 6, c8 = (j & 63) << 3;
            cvt8(h, sv_w + (size_t)row * DIMN + c8);
            *(uint4*)(Wv + (size_t)row * DIMN + c8) = *(const uint4*)h;
        } else {
            const int j = i - E6;
            const int row = j >> 6, c8 = (j & 63) << 3;
            cvt8(h, ss_w + (size_t)row * DIMN + c8);
            *(uint4*)(Ws + (size_t)row * DIMN + c8) = *(const uint4*)h;
        }
    }
}

// ---------------- mma.sync GEMM core -------------------------------------------------
#define TILEN   64
#define PITCH   144u
#define MATA    (128u * PITCH)
#define STAGEB  (MATA + 64u * PITCH)

template<int AMODE>
__device__ __forceinline__ void load_stage(
    uint32_t sb, int t,
    const __half* __restrict__ A, const __half* __restrict__ B,
    int row0, int col0, int K, int k0)
{
#pragma unroll
    for (int j = 0; j < 8; j++) {
        const int cid = j * 128 + t;
        const int r  = cid >> 3, ch = cid & 7;
        const uint32_t sa = sb + (uint32_t)(r * PITCH + ch * 16);
        if (AMODE == 0) {
            cp16(sa, A + (size_t)(row0 + r) * K + k0 + ch * 8);
        } else {
            const int grow = row0 + r;
            const int tap  = k0 >> 9;
            const int din0 = (k0 & 511) + ch * 8;
            const int s2   = (grow & 31) + tap - 2;
            const uint32_t ok = (s2 >= 0 && s2 < SEQ) ? 16u : 0u;
            const int srow = ok ? (grow + tap - 2) : grow;
            cp16z(sa, A + (size_t)srow * DIMN + din0, ok);
        }
    }
#pragma unroll
    for (int j = 0; j < 4; j++) {
        const int cid = j * 128 + t;
        const int r  = cid >> 3, ch = cid & 7;
        cp16(sb + MATA + (uint32_t)(r * PITCH + ch * 16),
             B + (size_t)(col0 + r) * K + k0 + ch * 8);
    }
}

// shared mainloop: accumulates A[row0.., K] x B[col0.., K]^T into acc
template<int AMODE>
__device__ __forceinline__ void gemm_core(
    uint32_t sbase, int t,
    const __half* __restrict__ A, const __half* __restrict__ B,
    int row0, int col0, int K,
    uint32_t a_off, uint32_t b_off, float acc[4][4][4])
{
    const int nch = K >> 6;

    load_stage<AMODE>(sbase, t, A, B, row0, col0, K, 0);
    cp_commit();

    uint32_t afr[2][4][4], bfr[2][4][2];

    for (int i = 0; i < nch; i++) {
        cp_wait<0>();
        __syncthreads();

        if (i + 1 < nch)
            load_stage<AMODE>(sbase + ((i + 1) & 1) * STAGEB, t, A, B,
                              row0, col0, K, (i + 1) * 64);
        cp_commit();

        const uint32_t sb = sbase + (uint32_t)(i & 1) * STAGEB;

#pragma unroll
        for (int mt = 0; mt < 4; mt++)
            ldmx4(afr[0][mt], sb + a_off + (uint32_t)(mt * (16 * PITCH)));
#pragma unroll
        for (int j = 0; j < 2; j++) {
            uint32_t r[4];
            ldmx4(r, sb + b_off + (uint32_t)(j * (16 * PITCH)));
            bfr[0][2 * j][0] = r[0]; bfr[0][2 * j][1] = r[1];
            bfr[0][2 * j + 1][0] = r[2]; bfr[0][2 * j + 1][1] = r[3];
        }

#pragma unroll
        for (int kk = 0; kk < 4; kk++) {
            const int cur = kk & 1, nxt = cur ^ 1;
            if (kk < 3) {
#pragma unroll
                for (int mt = 0; mt < 4; mt++)
                    ldmx4(afr[nxt][mt],
                          sb + a_off + (uint32_t)(mt * (16 * PITCH) + (kk + 1) * 32));
#pragma unroll
                for (int j = 0; j < 2; j++) {
                    uint32_t r[4];
                    ldmx4(r, sb + b_off + (uint32_t)(j * (16 * PITCH) + (kk + 1) * 32));
                    bfr[nxt][2 * j][0] = r[0]; bfr[nxt][2 * j][1] = r[1];
                    bfr[nxt][2 * j + 1][0] = r[2]; bfr[nxt][2 * j + 1][1] = r[3];
                }
            }
#pragma unroll
            for (int mt = 0; mt < 4; mt++)
#pragma unroll
                for (int nt = 0; nt < 4; nt++)
                    mma_f16(acc[mt][nt],
                            afr[cur][mt][0], afr[cur][mt][1],
                            afr[cur][mt][2], afr[cur][mt][3],
                            bfr[cur][nt][0], bfr[cur][nt][1]);
        }
    }
}

// EPI 1: C=acc+b, H=h(relu) | 2: H only | 3: C += 0.3*(acc+b) | 0: C=acc+b
// EPI 5: fused tail pair (z selects; K identical for both) |
// EPI 6: fused GEMM1+psl (y<32: GEMM1, K param; y>=32: psl, K=KPSL)
template<int AMODE, int EPI>
__global__ void __launch_bounds__(128, 3) gemm_mma(
    const __half* __restrict__ A, const __half* __restrict__ B,
    const float* __restrict__ bias, float* __restrict__ C,
    __half* __restrict__ H, int K,
    const __half* A2 = nullptr, const __half* B2 = nullptr,
    const float* bias2 = nullptr, float* C2 = nullptr)
{
    extern __shared__ char smem[];
    const uint32_t sbase = smem_u32(smem);
    const int t = threadIdx.x;
    const int wid = t >> 5, lane = t & 31;
    const int warp_m = wid >> 1, warp_n = wid & 1;
    const int tr = lane >> 2, tc = lane & 3;
    int row0 = blockIdx.y * 128;
    const int col0 = blockIdx.x * TILEN;

    bool second = false;
    if (EPI == 5 && blockIdx.z == 1) second = true;
    if (EPI == 6 && blockIdx.y >= 32) {
        second = true;
        row0 = (blockIdx.y - 32) * 128;
        K = KPSL;                       // psl branch only (EPI 5 keeps its K!)
    }
    if ((EPI == 5 || EPI == 6) && second) { A = A2; B = B2; bias = bias2; C = C2; }

    const uint32_t a_off = (uint32_t)((warp_m * 64 + (lane & 15)) * PITCH + (lane >> 4) * 16);
    const uint32_t b_off = MATA +
        (uint32_t)((warp_n * 32 + (lane & 7) + ((lane >> 4) << 3)) * PITCH + ((lane >> 3) & 1) * 16);

    float acc[4][4][4];
#pragma unroll
    for (int i = 0; i < 4; i++)
#pragma unroll
        for (int j = 0; j < 4; j++)
#pragma unroll
            for (int e = 0; e < 4; e++) acc[i][j][e] = 0.f;

    gemm_core<AMODE>(sbase, t, A, B, row0, col0, K, a_off, b_off, acc);

    // epilogue
#pragma unroll
    for (int mt = 0; mt < 4; mt++) {
        const int r0 = row0 + warp_m * 64 + mt * 16 + tr;
#pragma unroll
        for (int nt = 0; nt < 4; nt++) {
            const int cc = col0 + warp_n * 32 + nt * 8 + tc * 2;
            const float bx = __ldg(bias + cc), by = __ldg(bias + cc + 1);
            float2 v0 = make_float2(acc[mt][nt][0] + bx, acc[mt][nt][1] + by);
            float2 v1 = make_float2(acc[mt][nt][2] + bx, acc[mt][nt][3] + by);
            float* p0 = C + (size_t)r0 * DIMN + cc;
            float* p1 = C + (size_t)(r0 + 8) * DIMN + cc;
            if (EPI == 3) {
                float2 o0 = *(const float2*)p0;
                float2 o1 = *(const float2*)p1;
                v0.x = o0.x + 0.3f * v0.x;  v0.y = o0.y + 0.3f * v0.y;
                v1.x = o1.x + 0.3f * v1.x;  v1.y = o1.y + 0.3f * v1.y;
            }
            if (EPI != 2) {
                *(float2*)p0 = v0;
                *(float2*)p1 = v1;
            }
            if (EPI == 1 || EPI == 2 || (EPI == 6 && !second)) {
                __half2 h0, h1;
                h0.x = __float2half(fmaxf(v0.x, 0.f));
                h0.y = __float2half(fmaxf(v0.y, 0.f));
                h1.x = __float2half(fmaxf(v1.x, 0.f));
                h1.y = __float2half(fmaxf(v1.y, 0.f));
                *(__half2*)(H + (size_t)r0 * DIMN + cc)       = h0;
                *(__half2*)(H + (size_t)(r0 + 8) * DIMN + cc) = h1;
            }
        }
    }
}

// ---------------- tail stage A ------------------------------------------------------
__global__ void __launch_bounds__(256) tail_pre(
    const float* __restrict__ alpha_all,
    const float* __restrict__ att_mask,
    const float* __restrict__ ln_g, const float* __restrict__ ln_b,
    __half* __restrict__ sptH, __half* __restrict__ saggH)
{
    const int b    = blockIdx.x;
    const int t    = threadIdx.x;
    const int warp = t >> 5;
    const int lane = t & 31;

    __shared__ float spt [NTOP][DIMN];
    __shared__ float sagg[NTOP][DIMN];
    __shared__ float adj [SEQ][NTOP];
    __shared__ float sums[20];
    __shared__ int   idxs[NTOP];
    __shared__ float smask[SEQ];

    if (t < SEQ) smask[t] = att_mask[b * SEQ + t];
    __syncthreads();

    if (t < 20) {
        float s = 0.f;
        for (int si = 0; si < SEQ; si++)
            s = fmaf(alpha_all[((size_t)b * SEQ + si) * 20 + t], smask[si], s);
        sums[t] = s;
    }
    __syncthreads();

    if (t == 0) {
        unsigned used = 0;
        for (int k = 0; k < NTOP; k++) {
            int best = 0; float bv = -3.4e38f;
            for (int p = 0; p < 20; p++)
                if (!((used >> p) & 1u) && sums[p] > bv) { bv = sums[p]; best = p; }
            used |= (1u << best);
            idxs[k] = best;
        }
    }
    __syncthreads();

    for (int i = t; i < NTOP * DIMN; i += 256) {
        const int k = i >> 9, d = i & 511;
        spt[k][d] = g_psl[((size_t)b * 20 + idxs[k]) * DIMN + d];
    }
    __syncthreads();

    for (int pair = warp; pair < SEQ * NTOP; pair += 8) {
        const int s = pair / NTOP;
        const int k = pair - s * NTOP;
        const float* xr = g_X + ((size_t)b * SEQ + s) * DIMN;
        float acc = 0.f;
        for (int d = lane; d < DIMN; d += 32)
            acc = fmaf(xr[d], spt[k][d], acc);
#pragma unroll
        for (int o = 16; o > 0; o >>= 1)
            acc += __shfl_down_sync(0xffffffffu, acc, o);
        if (lane == 0) {
            const float v = acc * 0.04419417382415922f;
            adj[s][k] = (smask[s] > 0.f) ? v : -9.0e15f;
        }
    }
    __syncthreads();

    if (warp < NTOP) {
        const int k = warp;
        float v = adj[lane][k];
        float m = v;
#pragma unroll
        for (int o = 16; o > 0; o >>= 1)
            m = fmaxf(m, __shfl_xor_sync(0xffffffffu, m, o));
        const float e = expf(v - m);
        float ss = e;
#pragma unroll
        for (int o = 16; o > 0; o >>= 1)
            ss += __shfl_xor_sync(0xffffffffu, ss, o);
        adj[lane][k] = e / ss;
    }
    __syncthreads();

    for (int d = t; d < DIMN; d += 256) {
        float a[NTOP];
#pragma unroll
        for (int k = 0; k < NTOP; k++) a[k] = 0.f;
        for (int s = 0; s < SEQ; s++) {
            const float xv = g_X[((size_t)b * SEQ + s) * DIMN + d];
#pragma unroll
            for (int k = 0; k < NTOP; k++) a[k] = fmaf(xv, adj[s][k], a[k]);
        }
#pragma unroll
        for (int k = 0; k < NTOP; k++) sagg[k][d] = a[k];
    }
    __syncthreads();

    if (warp < NTOP) {
        const int k = warp;
        float sum = 0.f, sq = 0.f;
        for (int d = lane; d < DIMN; d += 32) {
            const float v = sagg[k][d];
            sum += v;
            sq = fmaf(v, v, sq);
        }
#pragma unroll
        for (int o = 16; o > 0; o >>= 1) {
            sum += __shfl_xor_sync(0xffffffffu, sum, o);
            sq  += __shfl_xor_sync(0xffffffffu, sq,  o);
        }
        const float mu  = sum * (1.f / DIMN);
        const float var = sq * (1.f / DIMN) - mu * mu;
        const float inv = rsqrtf(var + 1e-5f);
        for (int d = lane; d < DIMN; d += 32)
            sagg[k][d] = (sagg[k][d] - mu) * inv * ln_g[d] + ln_b[d];
    }
    __syncthreads();

    for (int i = t; i < NTOP * DIMN; i += 256) {
        const int k = i >> 9, d = i & 511;
        const size_t o = ((size_t)(b * NTOP + k)) * DIMN + d;
        sptH [o] = __float2half(spt[k][d]);
        saggH[o] = __float2half(sagg[k][d]);
    }
}

// ---------------- tail stage B -------------------------------------------------------
__global__ void __launch_bounds__(256) tail_post(
    const float* __restrict__ V, const float* __restrict__ S,
    const float* __restrict__ cl_w, const float* __restrict__ cl_b,
    float* __restrict__ out)
{
    const int row  = blockIdx.x * 8 + (threadIdx.x >> 5);
    const int lane = threadIdx.x & 31;
    const float* v = V + (size_t)row * DIMN;
    const float* s = S + (size_t)row * DIMN;
    float acc = 0.f;
#pragma unroll 4
    for (int d = lane; d < DIMN; d += 32)
        acc = fmaf(tanhf(v[d]) * tanhf(s[d]), cl_w[d], acc);
#pragma unroll
    for (int o = 16; o > 0; o >>= 1)
        acc += __shfl_xor_sync(0xffffffffu, acc, o);
    if (lane == 0)
        out[row] = 1.f / (1.f + expf(-(acc + cl_b[0])));
}

// ---------------- launch --------------------------------------------------------------
extern "C" void kernel_launch(void* const* d_in, const int* in_sizes, int n_in,
                              void* d_out, int out_size)
{
    const float* inputs   = (const float*)d_in[0];
    const float* obj      = (const float*)d_in[2];
    const float* motion   = (const float*)d_in[3];
    const float* att_mask = (const float*)d_in[4];
    const float* alpha    = (const float*)d_in[5];
    const float* conv_w   = (const float*)d_in[6];
    const float* conv_b   = (const float*)d_in[7];
    const float* res_w1   = (const float*)d_in[8];
    const float* res_b1   = (const float*)d_in[9];
    const float* res_w2   = (const float*)d_in[10];
    const float* res_b2   = (const float*)d_in[11];
    const float* psl_w    = (const float*)d_in[12];
    const float* psl_b    = (const float*)d_in[13];
    const float* ln_g     = (const float*)d_in[14];
    const float* ln_b     = (const float*)d_in[15];
    const float* sv_w     = (const float*)d_in[16];
    const float* sv_b     = (const float*)d_in[17];
    const float* ss_w     = (const float*)d_in[18];
    const float* ss_b     = (const float*)d_in[19];
    const float* cl_w     = (const float*)d_in[20];
    const float* cl_b     = (const float*)d_in[21];
    float* out = (float*)d_out;

    float *X, *PSL, *V, *Sv;
    __half *Xh, *Y1h, *A, *Ap, *Wc, *W1, *W2, *Wp, *Wv, *Ws, *SptH, *SaggH;
    cudaGetSymbolAddress((void**)&X,    g_X);
    cudaGetSymbolAddress((void**)&Xh,   g_Xh);
    cudaGetSymbolAddress((void**)&Y1h,  g_Y1h);
    cudaGetSymbolAddress((void**)&PSL,  g_psl);
    cudaGetSymbolAddress((void**)&A,    g_A);
    cudaGetSymbolAddress((void**)&Ap,   g_Ap);
    cudaGetSymbolAddress((void**)&Wc,   g_Wc);
    cudaGetSymbolAddress((void**)&W1,   g_W1);
    cudaGetSymbolAddress((void**)&W2,   g_W2);
    cudaGetSymbolAddress((void**)&Wp,   g_Wp);
    cudaGetSymbolAddress((void**)&Wv,   g_Wv);
    cudaGetSymbolAddress((void**)&Ws,   g_Ws);
    cudaGetSymbolAddress((void**)&SptH, g_SptH);
    cudaGetSymbolAddress((void**)&SaggH,g_SaggH);
    cudaGetSymbolAddress((void**)&V,    g_V);
    cudaGetSymbolAddress((void**)&Sv,   g_Sv);

    const int SMEM_BYTES = 2 * (int)STAGEB;   // 55296
    cudaFuncSetAttribute(gemm_mma<0,6>, cudaFuncAttributeMaxDynamicSharedMemorySize, SMEM_BYTES);
    cudaFuncSetAttribute(gemm_mma<1,2>, cudaFuncAttributeMaxDynamicSharedMemorySize, SMEM_BYTES);
    cudaFuncSetAttribute(gemm_mma<1,3>, cudaFuncAttributeMaxDynamicSharedMemorySize, SMEM_BYTES);
    cudaFuncSetAttribute(gemm_mma<0,5>, cudaFuncAttributeMaxDynamicSharedMemorySize, SMEM_BYTES);

    const dim3 blk(128);
    const dim3 gBig1(DIMN / TILEN, 32 + 20);  // 416 CTAs: GEMM1 (y<32) + psl (y>=32)
    const dim3 gBig (DIMN / TILEN, 32);       // 256 CTAs
    const dim3 gTail(DIMN / TILEN, 6, 2);     //  96 CTAs

    // #0: all conversions
    mega_convert<<<1184, 256>>>(inputs, conv_w, res_w1, res_w2, psl_w,
                                obj, motion, sv_w, ss_w,
                                A, Wc, W1, W2, Wp, Ap, Wv, Ws);

    // #1: fused GEMM1 + psl GEMM
    gemm_mma<0, 6><<<gBig1, blk, SMEM_BYTES>>>(A, Wc, conv_b, X, Xh, KBIGP,
                                               Ap, Wp, psl_b, PSL);

    // #2/#3: conv GEMM chain
    gemm_mma<1, 2><<<gBig, blk, SMEM_BYTES>>>(Xh,  W1, res_b1, X, Y1h, KCONV);
    gemm_mma<1, 3><<<gBig, blk, SMEM_BYTES>>>(Y1h, W2, res_b2, X, Xh,  KCONV);

    // #4: per-batch attention/topk/LN
    tail_pre<<<BS_, 256>>>(alpha, att_mask, ln_g, ln_b, SptH, SaggH);

    // #5: both tail GEMMs in one launch
    gemm_mma<0, 5><<<gTail, blk, SMEM_BYTES>>>(SptH, Wv, sv_b, V, Xh /*unused*/, DIMN,
                                               SaggH, Ws, ss_b, Sv);

    // #6: scoring
    tail_post<<<96, 256>>>(V, Sv, cl_w, cl_b, out);
}